// round 4
// baseline (speedup 1.0000x reference)
#include <cuda_runtime.h>
#include <math.h>
#include <stdint.h>

// Problem constants
#define DM   512          // d_model = dim_k = dim_v
#define SEQ  2048
#define BB   2
#define NH   8
#define HD   64
#define MTOK (BB*SEQ)     // 4096 tokens
#define NG   (NH*BB)      // 16 attention groups (head-major view slices)

#define NORMF 0.04419417382415922f  // 1/sqrt(512)

// Scratch (static device globals; allocation is forbidden)
__device__ float g_Qp[MTOK * DM];
__device__ float g_Kp[MTOK * DM];
__device__ float g_Vp[MTOK * DM];
__device__ float g_AO[MTOK * DM];

// ---------------------------------------------------------------------------
// NT GEMM (projections): C[m,n] = sum_k A[m,k]*B[n,k] (+bias). FFMA path.
// ---------------------------------------------------------------------------
__global__ __launch_bounds__(256) void gemm_nt(
    const float* __restrict__ A, const float* __restrict__ Bm,
    const float* __restrict__ bias, float* __restrict__ C,
    int lda, int ldb, int ldc)
{
    __shared__ float As[8][128];
    __shared__ float Bs[8][128];

    const int tid = threadIdx.x;
    const int tr  = tid >> 4;
    const int tc  = tid & 15;
    const int m0  = blockIdx.y * 128;
    const int n0  = blockIdx.x * 128;
    const int lrow = tid >> 1;
    const int lseg = (tid & 1) * 4;

    float acc[8][8];
    #pragma unroll
    for (int i = 0; i < 8; i++)
        #pragma unroll
        for (int j = 0; j < 8; j++) acc[i][j] = 0.f;

    for (int k0 = 0; k0 < DM; k0 += 8) {
        float4 av = *(const float4*)&A [(long long)(m0 + lrow) * lda + k0 + lseg];
        float4 bv = *(const float4*)&Bm[(long long)(n0 + lrow) * ldb + k0 + lseg];
        __syncthreads();
        As[lseg + 0][lrow] = av.x; As[lseg + 1][lrow] = av.y;
        As[lseg + 2][lrow] = av.z; As[lseg + 3][lrow] = av.w;
        Bs[lseg + 0][lrow] = bv.x; Bs[lseg + 1][lrow] = bv.y;
        Bs[lseg + 2][lrow] = bv.z; Bs[lseg + 3][lrow] = bv.w;
        __syncthreads();
        #pragma unroll
        for (int kk = 0; kk < 8; kk++) {
            float4 a0 = *(const float4*)&As[kk][tr * 4];
            float4 a1 = *(const float4*)&As[kk][64 + tr * 4];
            float4 b0 = *(const float4*)&Bs[kk][tc * 4];
            float4 b1 = *(const float4*)&Bs[kk][64 + tc * 4];
            float a[8] = {a0.x,a0.y,a0.z,a0.w,a1.x,a1.y,a1.z,a1.w};
            float b[8] = {b0.x,b0.y,b0.z,b0.w,b1.x,b1.y,b1.z,b1.w};
            #pragma unroll
            for (int i = 0; i < 8; i++)
                #pragma unroll
                for (int j = 0; j < 8; j++)
                    acc[i][j] = fmaf(a[i], b[j], acc[i][j]);
        }
    }

    float bb[8];
    #pragma unroll
    for (int j = 0; j < 4; j++) {
        bb[j]     = bias[n0 + tc * 4 + j];
        bb[4 + j] = bias[n0 + 64 + tc * 4 + j];
    }

    #pragma unroll
    for (int i = 0; i < 8; i++) {
        int mi = m0 + ((i < 4) ? (tr * 4 + i) : (64 + tr * 4 + i - 4));
        float4 o0 = make_float4(acc[i][0] + bb[0], acc[i][1] + bb[1],
                                acc[i][2] + bb[2], acc[i][3] + bb[3]);
        float4 o1 = make_float4(acc[i][4] + bb[4], acc[i][5] + bb[5],
                                acc[i][6] + bb[6], acc[i][7] + bb[7]);
        *(float4*)&C[(long long)mi * ldc + n0 + tc * 4]      = o0;
        *(float4*)&C[(long long)mi * ldc + n0 + 64 + tc * 4] = o1;
    }
}

// ---------------------------------------------------------------------------
// tf32 mma.sync.m16n8k8 wrapper + 3xTF32 split helpers
// ---------------------------------------------------------------------------
__device__ __forceinline__ void mma_tf32(float* c, const uint32_t* a, const uint32_t* b)
{
    asm volatile(
        "mma.sync.aligned.m16n8k8.row.col.f32.tf32.tf32.f32 "
        "{%0,%1,%2,%3}, {%4,%5,%6,%7}, {%8,%9}, {%0,%1,%2,%3};\n"
        : "+f"(c[0]), "+f"(c[1]), "+f"(c[2]), "+f"(c[3])
        : "r"(a[0]), "r"(a[1]), "r"(a[2]), "r"(a[3]), "r"(b[0]), "r"(b[1]));
}

__device__ __forceinline__ uint32_t to_tf32(float x)
{
    uint32_t r;
    asm("cvt.rna.tf32.f32 %0, %1;\n" : "=r"(r) : "f"(x));
    return r;
}

// split x into tf32 hi + tf32 lo (x ~= hi + lo to ~2^-22 relative)
__device__ __forceinline__ void split_tf32(float x, uint32_t& hi, uint32_t& lo)
{
    hi = to_tf32(x);
    lo = to_tf32(x - __uint_as_float(hi));
}

// 3-term product accumulate: C += hi(A)hi(B) + hi(A)lo(B) + lo(A)hi(B)
__device__ __forceinline__ void mma3(float* c,
                                     const uint32_t* ah, const uint32_t* al,
                                     const uint32_t* bh, const uint32_t* bl)
{
    mma_tf32(c, ah, bl);
    mma_tf32(c, al, bh);
    mma_tf32(c, ah, bh);
}

// ---------------------------------------------------------------------------
// Fused two-pass attention (mean-threshold masked softmax), 3xTF32 precision.
// Per CTA: 64 query rows of one group. 4 warps x 16 rows.
// ---------------------------------------------------------------------------
#define QSTR 68   // padded stride for Q/K/P tiles
#define VSTR 72   // padded stride for V tile
#define SM_FLOATS (2*64*QSTR + 64*QSTR + 64*VSTR + 4*16*QSTR)  // Qhi,Qlo,K,V,P
#define SM_BYTES  (SM_FLOATS * 4)

__global__ __launch_bounds__(128) void attn_fused(
    const float* __restrict__ Qp, const float* __restrict__ Kp,
    const float* __restrict__ Vp, float* __restrict__ AO)
{
    extern __shared__ float sm[];
    float* sQh = sm;                   // [64][QSTR] Q hi (as float bits of tf32)
    float* sQl = sQh + 64 * QSTR;      // [64][QSTR] Q lo
    float* sK  = sQl + 64 * QSTR;      // [64][QSTR] K fp32
    float* sV  = sK  + 64 * QSTR;      // [64][VSTR] V fp32
    float* sPall = sV + 64 * VSTR;     // 4 x [16][QSTR] P fp32

    const int tid  = threadIdx.x;
    const int warp = tid >> 5;
    const int lane = tid & 31;
    const int g4   = lane >> 2;
    const int t4   = lane & 3;

    const int mt  = blockIdx.x;
    const int grp = blockIdx.y;
    const float* Qg = Qp + (size_t)grp * SEQ * HD;
    const float* Kg = Kp + (size_t)grp * SEQ * HD;
    const float* Vg = Vp + (size_t)grp * SEQ * HD;
    float*       Og = AO + (size_t)grp * SEQ * HD;

    const int m0   = mt * 64;
    const int wrow = warp * 16;
    float* sP = sPall + warp * 16 * QSTR;

    // Load Q tile, pre-scale, split into hi/lo
    #pragma unroll
    for (int i = 0; i < 8; i++) {
        int j = tid + i * 128;
        int r = j >> 4, c4 = (j & 15) << 2;
        float4 v = *(const float4*)&Qg[(size_t)(m0 + r) * HD + c4];
        float xs[4] = {v.x * NORMF, v.y * NORMF, v.z * NORMF, v.w * NORMF};
        #pragma unroll
        for (int e = 0; e < 4; e++) {
            uint32_t h, l; split_tf32(xs[e], h, l);
            sQh[r * QSTR + c4 + e] = __uint_as_float(h);
            sQl[r * QSTR + c4 + e] = __uint_as_float(l);
        }
    }

    // ---------------- pass 1: row sum & max ----------------
    float sum0 = 0.f, sum1 = 0.f, mx0 = -3.4e38f, mx1 = -3.4e38f;

    for (int kt = 0; kt < SEQ / 64; kt++) {
        __syncthreads();
        #pragma unroll
        for (int i = 0; i < 8; i++) {
            int j = tid + i * 128;
            int r = j >> 4, c4 = (j & 15) << 2;
            *(float4*)&sK[r * QSTR + c4] =
                *(const float4*)&Kg[(size_t)(kt * 64 + r) * HD + c4];
        }
        __syncthreads();

        float sacc[8][4];
        #pragma unroll
        for (int j = 0; j < 8; j++)
            #pragma unroll
            for (int c = 0; c < 4; c++) sacc[j][c] = 0.f;

        #pragma unroll
        for (int kk = 0; kk < 8; kk++) {
            const int k0 = kk * 8;
            uint32_t ah[4], al[4];
            ah[0] = __float_as_uint(sQh[(wrow + g4)     * QSTR + k0 + t4]);
            ah[1] = __float_as_uint(sQh[(wrow + g4 + 8) * QSTR + k0 + t4]);
            ah[2] = __float_as_uint(sQh[(wrow + g4)     * QSTR + k0 + t4 + 4]);
            ah[3] = __float_as_uint(sQh[(wrow + g4 + 8) * QSTR + k0 + t4 + 4]);
            al[0] = __float_as_uint(sQl[(wrow + g4)     * QSTR + k0 + t4]);
            al[1] = __float_as_uint(sQl[(wrow + g4 + 8) * QSTR + k0 + t4]);
            al[2] = __float_as_uint(sQl[(wrow + g4)     * QSTR + k0 + t4 + 4]);
            al[3] = __float_as_uint(sQl[(wrow + g4 + 8) * QSTR + k0 + t4 + 4]);
            #pragma unroll
            for (int j = 0; j < 8; j++) {
                uint32_t bh[2], bl[2];
                split_tf32(sK[(j * 8 + g4) * QSTR + k0 + t4],     bh[0], bl[0]);
                split_tf32(sK[(j * 8 + g4) * QSTR + k0 + t4 + 4], bh[1], bl[1]);
                mma3(sacc[j], ah, al, bh, bl);
            }
        }
        #pragma unroll
        for (int j = 0; j < 8; j++) {
            sum0 += sacc[j][0] + sacc[j][1];
            sum1 += sacc[j][2] + sacc[j][3];
            mx0 = fmaxf(mx0, fmaxf(sacc[j][0], sacc[j][1]));
            mx1 = fmaxf(mx1, fmaxf(sacc[j][2], sacc[j][3]));
        }
    }
    #pragma unroll
    for (int o = 1; o <= 2; o <<= 1) {
        sum0 += __shfl_xor_sync(0xffffffffu, sum0, o);
        sum1 += __shfl_xor_sync(0xffffffffu, sum1, o);
        mx0 = fmaxf(mx0, __shfl_xor_sync(0xffffffffu, mx0, o));
        mx1 = fmaxf(mx1, __shfl_xor_sync(0xffffffffu, mx1, o));
    }
    const float mean0 = sum0 * (1.f / (float)SEQ);
    const float mean1 = sum1 * (1.f / (float)SEQ);

    // ---------------- pass 2: masked exp + PV ----------------
    float oacc[8][4];
    #pragma unroll
    for (int j = 0; j < 8; j++)
        #pragma unroll
        for (int c = 0; c < 4; c++) oacc[j][c] = 0.f;
    float den0 = 0.f, den1 = 0.f;

    for (int kt = 0; kt < SEQ / 64; kt++) {
        __syncthreads();
        #pragma unroll
        for (int i = 0; i < 8; i++) {
            int j = tid + i * 128;
            int r = j >> 4, c4 = (j & 15) << 2;
            *(float4*)&sK[r * QSTR + c4] =
                *(const float4*)&Kg[(size_t)(kt * 64 + r) * HD + c4];
            *(float4*)&sV[r * VSTR + c4] =
                *(const float4*)&Vg[(size_t)(kt * 64 + r) * HD + c4];
        }
        __syncthreads();

        float sacc[8][4];
        #pragma unroll
        for (int j = 0; j < 8; j++)
            #pragma unroll
            for (int c = 0; c < 4; c++) sacc[j][c] = 0.f;

        #pragma unroll
        for (int kk = 0; kk < 8; kk++) {
            const int k0 = kk * 8;
            uint32_t ah[4], al[4];
            ah[0] = __float_as_uint(sQh[(wrow + g4)     * QSTR + k0 + t4]);
            ah[1] = __float_as_uint(sQh[(wrow + g4 + 8) * QSTR + k0 + t4]);
            ah[2] = __float_as_uint(sQh[(wrow + g4)     * QSTR + k0 + t4 + 4]);
            ah[3] = __float_as_uint(sQh[(wrow + g4 + 8) * QSTR + k0 + t4 + 4]);
            al[0] = __float_as_uint(sQl[(wrow + g4)     * QSTR + k0 + t4]);
            al[1] = __float_as_uint(sQl[(wrow + g4 + 8) * QSTR + k0 + t4]);
            al[2] = __float_as_uint(sQl[(wrow + g4)     * QSTR + k0 + t4 + 4]);
            al[3] = __float_as_uint(sQl[(wrow + g4 + 8) * QSTR + k0 + t4 + 4]);
            #pragma unroll
            for (int j = 0; j < 8; j++) {
                uint32_t bh[2], bl[2];
                split_tf32(sK[(j * 8 + g4) * QSTR + k0 + t4],     bh[0], bl[0]);
                split_tf32(sK[(j * 8 + g4) * QSTR + k0 + t4 + 4], bh[1], bl[1]);
                mma3(sacc[j], ah, al, bh, bl);
            }
        }

        // mask + exp -> P (per-warp smem buffer), accumulate denominators
        #pragma unroll
        for (int j = 0; j < 8; j++) {
            const int col = j * 8 + 2 * t4;
            float p0 = (sacc[j][0] > mean0) ? __expf(sacc[j][0] - mx0) : 0.f;
            float p1 = (sacc[j][1] > mean0) ? __expf(sacc[j][1] - mx0) : 0.f;
            float p2 = (sacc[j][2] > mean1) ? __expf(sacc[j][2] - mx1) : 0.f;
            float p3 = (sacc[j][3] > mean1) ? __expf(sacc[j][3] - mx1) : 0.f;
            den0 += p0 + p1;
            den1 += p2 + p3;
            sP[g4       * QSTR + col]     = p0;
            sP[g4       * QSTR + col + 1] = p1;
            sP[(g4 + 8) * QSTR + col]     = p2;
            sP[(g4 + 8) * QSTR + col + 1] = p3;
        }
        __syncwarp();

        // O += P @ V  (3xTF32)
        #pragma unroll
        for (int kk = 0; kk < 8; kk++) {
            const int k0 = kk * 8;
            uint32_t ah[4], al[4];
            split_tf32(sP[g4       * QSTR + k0 + t4],     ah[0], al[0]);
            split_tf32(sP[(g4 + 8) * QSTR + k0 + t4],     ah[1], al[1]);
            split_tf32(sP[g4       * QSTR + k0 + t4 + 4], ah[2], al[2]);
            split_tf32(sP[(g4 + 8) * QSTR + k0 + t4 + 4], ah[3], al[3]);
            #pragma unroll
            for (int j = 0; j < 8; j++) {
                uint32_t bh[2], bl[2];
                split_tf32(sV[(k0 + t4)     * VSTR + j * 8 + g4], bh[0], bl[0]);
                split_tf32(sV[(k0 + t4 + 4) * VSTR + j * 8 + g4], bh[1], bl[1]);
                mma3(oacc[j], ah, al, bh, bl);
            }
        }
    }

    // reduce denominators across quad, normalize, write out
    #pragma unroll
    for (int o = 1; o <= 2; o <<= 1) {
        den0 += __shfl_xor_sync(0xffffffffu, den0, o);
        den1 += __shfl_xor_sync(0xffffffffu, den1, o);
    }
    const float inv0 = 1.f / den0;
    const float inv1 = 1.f / den1;

    const int row0 = m0 + wrow + g4;
    const int row1 = row0 + 8;
    #pragma unroll
    for (int j = 0; j < 8; j++) {
        const int col = j * 8 + 2 * t4;
        Og[(size_t)row0 * HD + col]     = oacc[j][0] * inv0;
        Og[(size_t)row0 * HD + col + 1] = oacc[j][1] * inv0;
        Og[(size_t)row1 * HD + col]     = oacc[j][2] * inv1;
        Og[(size_t)row1 * HD + col + 1] = oacc[j][3] * inv1;
    }
}

// ---------------------------------------------------------------------------
// Launch
// ---------------------------------------------------------------------------
extern "C" void kernel_launch(void* const* d_in, const int* in_sizes, int n_in,
                              void* d_out, int out_size)
{
    const float* x   = (const float*)d_in[0];
    const float* y   = (const float*)d_in[1];
    const float* q_w = (const float*)d_in[2];
    const float* q_b = (const float*)d_in[3];
    const float* k_w = (const float*)d_in[4];
    const float* k_b = (const float*)d_in[5];
    const float* v_w = (const float*)d_in[6];
    const float* v_b = (const float*)d_in[7];
    const float* o_w = (const float*)d_in[8];
    const float* o_b = (const float*)d_in[9];
    float* out = (float*)d_out;

    float *Qp, *Kp, *Vp, *AO;
    cudaGetSymbolAddress((void**)&Qp, g_Qp);
    cudaGetSymbolAddress((void**)&Kp, g_Kp);
    cudaGetSymbolAddress((void**)&Vp, g_Vp);
    cudaGetSymbolAddress((void**)&AO, g_AO);

    static int smem_set = 0;
    if (!smem_set) {
        cudaFuncSetAttribute(attn_fused,
                             cudaFuncAttributeMaxDynamicSharedMemorySize, SM_BYTES);
        smem_set = 1;
    }

    dim3 blk(256);

    // QKV projections: [4096,512] @ [512,512]^T + bias
    gemm_nt<<<dim3(4, 32), blk>>>(x, q_w, q_b, Qp, DM, DM, DM);
    gemm_nt<<<dim3(4, 32), blk>>>(y, k_w, k_b, Kp, DM, DM, DM);
    gemm_nt<<<dim3(4, 32), blk>>>(y, v_w, v_b, Vp, DM, DM, DM);

    // Fused attention: scores -> mean-threshold mask -> softmax -> P@V
    attn_fused<<<dim3(SEQ / 64, NG), 128, SM_BYTES>>>(Qp, Kp, Vp, AO);

    // Output projection: [4096,512] @ [512,512]^T + bias -> d_out
    gemm_nt<<<dim3(4, 32), blk>>>(AO, o_w, o_b, out, DM, DM, DM);
}

// round 5
// speedup vs baseline: 1.3982x; 1.3982x over previous
#include <cuda_runtime.h>
#include <math.h>
#include <stdint.h>

// Problem constants
#define DM   512
#define SEQ  2048
#define BB   2
#define NH   8
#define HD   64
#define MTOK (BB*SEQ)     // 4096 tokens
#define NG   (NH*BB)      // 16 attention groups

#define NORMF 0.04419417382415922f  // 1/sqrt(512)

// Scratch (static device globals; allocation is forbidden)
__device__ float g_Qp[MTOK * DM];
__device__ float g_Kp[MTOK * DM];
__device__ float g_Vp[MTOK * DM];
__device__ float g_AO[MTOK * DM];
__device__ float g_KsumP[NG * 8 * HD];   // per-group, 8 row-chunks, col-sums of K

// ---------------------------------------------------------------------------
// NT GEMM (projections): C[m,n] = sum_k A[m,k]*B[n,k] (+bias). FFMA path.
// ---------------------------------------------------------------------------
__global__ __launch_bounds__(256) void gemm_nt(
    const float* __restrict__ A, const float* __restrict__ Bm,
    const float* __restrict__ bias, float* __restrict__ C,
    int lda, int ldb, int ldc)
{
    __shared__ float As[8][128];
    __shared__ float Bs[8][128];

    const int tid = threadIdx.x;
    const int tr  = tid >> 4;
    const int tc  = tid & 15;
    const int m0  = blockIdx.y * 128;
    const int n0  = blockIdx.x * 128;
    const int lrow = tid >> 1;
    const int lseg = (tid & 1) * 4;

    float acc[8][8];
    #pragma unroll
    for (int i = 0; i < 8; i++)
        #pragma unroll
        for (int j = 0; j < 8; j++) acc[i][j] = 0.f;

    for (int k0 = 0; k0 < DM; k0 += 8) {
        float4 av = *(const float4*)&A [(long long)(m0 + lrow) * lda + k0 + lseg];
        float4 bv = *(const float4*)&Bm[(long long)(n0 + lrow) * ldb + k0 + lseg];
        __syncthreads();
        As[lseg + 0][lrow] = av.x; As[lseg + 1][lrow] = av.y;
        As[lseg + 2][lrow] = av.z; As[lseg + 3][lrow] = av.w;
        Bs[lseg + 0][lrow] = bv.x; Bs[lseg + 1][lrow] = bv.y;
        Bs[lseg + 2][lrow] = bv.z; Bs[lseg + 3][lrow] = bv.w;
        __syncthreads();
        #pragma unroll
        for (int kk = 0; kk < 8; kk++) {
            float4 a0 = *(const float4*)&As[kk][tr * 4];
            float4 a1 = *(const float4*)&As[kk][64 + tr * 4];
            float4 b0 = *(const float4*)&Bs[kk][tc * 4];
            float4 b1 = *(const float4*)&Bs[kk][64 + tc * 4];
            float a[8] = {a0.x,a0.y,a0.z,a0.w,a1.x,a1.y,a1.z,a1.w};
            float b[8] = {b0.x,b0.y,b0.z,b0.w,b1.x,b1.y,b1.z,b1.w};
            #pragma unroll
            for (int i = 0; i < 8; i++)
                #pragma unroll
                for (int j = 0; j < 8; j++)
                    acc[i][j] = fmaf(a[i], b[j], acc[i][j]);
        }
    }

    float bb[8];
    #pragma unroll
    for (int j = 0; j < 4; j++) {
        bb[j]     = bias[n0 + tc * 4 + j];
        bb[4 + j] = bias[n0 + 64 + tc * 4 + j];
    }

    #pragma unroll
    for (int i = 0; i < 8; i++) {
        int mi = m0 + ((i < 4) ? (tr * 4 + i) : (64 + tr * 4 + i - 4));
        float4 o0 = make_float4(acc[i][0] + bb[0], acc[i][1] + bb[1],
                                acc[i][2] + bb[2], acc[i][3] + bb[3]);
        float4 o1 = make_float4(acc[i][4] + bb[4], acc[i][5] + bb[5],
                                acc[i][6] + bb[6], acc[i][7] + bb[7]);
        *(float4*)&C[(long long)mi * ldc + n0 + tc * 4]      = o0;
        *(float4*)&C[(long long)mi * ldc + n0 + 64 + tc * 4] = o1;
    }
}

// ---------------------------------------------------------------------------
// K column-sum partials: KsumP[g][chunk][d] = sum over 256 rows of K[g][.,d]
// ---------------------------------------------------------------------------
__global__ __launch_bounds__(256) void ksum_kernel(const float* __restrict__ Kp,
                                                   float* __restrict__ out)
{
    const int g  = blockIdx.x;
    const int ch = blockIdx.y;
    const int d  = threadIdx.x & 63;
    const int rc = threadIdx.x >> 6;      // 0..3
    const float* Kg = Kp + ((size_t)g * SEQ + ch * 256) * HD;
    float s = 0.f;
    #pragma unroll 8
    for (int r = rc; r < 256; r += 4) s += Kg[r * HD + d];
    __shared__ float red[256];
    red[threadIdx.x] = s;
    __syncthreads();
    if (rc == 0)
        out[(g * 8 + ch) * HD + d] = red[d] + red[64 + d] + red[128 + d] + red[192 + d];
}

// ---------------------------------------------------------------------------
// tf32 mma.sync.m16n8k8 + split helpers
// ---------------------------------------------------------------------------
__device__ __forceinline__ void mma_tf32(float* c, const uint32_t* a, const uint32_t* b)
{
    asm volatile(
        "mma.sync.aligned.m16n8k8.row.col.f32.tf32.tf32.f32 "
        "{%0,%1,%2,%3}, {%4,%5,%6,%7}, {%8,%9}, {%0,%1,%2,%3};\n"
        : "+f"(c[0]), "+f"(c[1]), "+f"(c[2]), "+f"(c[3])
        : "r"(a[0]), "r"(a[1]), "r"(a[2]), "r"(a[3]), "r"(b[0]), "r"(b[1]));
}

__device__ __forceinline__ uint32_t to_tf32(float x)
{
    uint32_t r;
    asm("cvt.rna.tf32.f32 %0, %1;\n" : "=r"(r) : "f"(x));
    return r;
}

__device__ __forceinline__ void split_tf32(float x, float& hi, float& lo)
{
    hi = __uint_as_float(to_tf32(x));
    lo = x - hi;                 // exact; HW truncates low bits at mma time
}

__device__ __forceinline__ void mma3(float* c,
                                     const uint32_t* ah, const uint32_t* al,
                                     const uint32_t* bh, const uint32_t* bl)
{
    mma_tf32(c, ah, bl);
    mma_tf32(c, al, bh);
    mma_tf32(c, ah, bh);
}

// ---------------------------------------------------------------------------
// Single-pass fused attention, 3xTF32 with pre-split operands.
// CTA = 64 query rows of one group; 4 warps x 16 rows; streams 32 K/V tiles.
// mean from precomputed K column sums; exp without max-shift (scores bounded).
// ---------------------------------------------------------------------------
#define KSTR 68
#define VSTR 72
#define SM_FLOATS (2*64*KSTR + 2*64*VSTR + 2*4*16*KSTR)
#define SM_BYTES  (SM_FLOATS * 4)          // 106496 B

__global__ __launch_bounds__(128, 2) void attn_fused(
    const float* __restrict__ Qp, const float* __restrict__ Kp,
    const float* __restrict__ Vp, const float* __restrict__ KsP,
    float* __restrict__ AO)
{
    extern __shared__ float sm[];
    float* sKh = sm;                         // [64][KSTR]
    float* sKl = sKh + 64 * KSTR;
    float* sVh = sKl + 64 * KSTR;            // [64][VSTR]
    float* sVl = sVh + 64 * VSTR;
    float* sPh_all = sVl + 64 * VSTR;        // 4 x [16][KSTR]
    float* sPl_all = sPh_all + 4 * 16 * KSTR;

    const int tid  = threadIdx.x;
    const int warp = tid >> 5;
    const int lane = tid & 31;
    const int g4   = lane >> 2;
    const int t4   = lane & 3;

    const int mt  = blockIdx.x;
    const int grp = blockIdx.y;
    const float* Qg = Qp + (size_t)grp * SEQ * HD;
    const float* Kg = Kp + (size_t)grp * SEQ * HD;
    const float* Vg = Vp + (size_t)grp * SEQ * HD;
    float*       Og = AO + (size_t)grp * SEQ * HD;

    const int m0 = mt * 64;
    const int wrow = warp * 16;
    float* sPh = sPh_all + warp * 16 * KSTR;
    float* sPl = sPl_all + warp * 16 * KSTR;

    // --- Q fragments (registers) + row means via K column-sums ---
    const int row0 = m0 + wrow + g4;
    const int row1 = row0 + 8;
    uint32_t qah[8][4], qal[8][4];
    float mdot0 = 0.f, mdot1 = 0.f;

    #pragma unroll
    for (int kk = 0; kk < 8; kk++) {
        #pragma unroll
        for (int e = 0; e < 2; e++) {
            const int col = kk * 8 + t4 + e * 4;
            float ks = 0.f;
            #pragma unroll
            for (int c = 0; c < 8; c++)
                ks += KsP[(grp * 8 + c) * HD + col];
            float q0 = Qg[(size_t)row0 * HD + col];
            float q1 = Qg[(size_t)row1 * HD + col];
            mdot0 += q0 * ks;
            mdot1 += q1 * ks;
            float h, l;
            split_tf32(q0 * NORMF, h, l);
            qah[kk][e * 2] = __float_as_uint(h);
            qal[kk][e * 2] = __float_as_uint(l);
            split_tf32(q1 * NORMF, h, l);
            qah[kk][e * 2 + 1] = __float_as_uint(h);
            qal[kk][e * 2 + 1] = __float_as_uint(l);
        }
    }
    #pragma unroll
    for (int o = 1; o <= 2; o <<= 1) {
        mdot0 += __shfl_xor_sync(0xffffffffu, mdot0, o);
        mdot1 += __shfl_xor_sync(0xffffffffu, mdot1, o);
    }
    const float mean0 = mdot0 * (NORMF / (float)SEQ);
    const float mean1 = mdot1 * (NORMF / (float)SEQ);

    // --- streaming loop ---
    float oacc[8][4];
    #pragma unroll
    for (int j = 0; j < 8; j++)
        #pragma unroll
        for (int c = 0; c < 4; c++) oacc[j][c] = 0.f;
    float den0 = 0.f, den1 = 0.f;

    for (int kt = 0; kt < SEQ / 64; kt++) {
        __syncthreads();
        // cooperative load + single split of K and V tiles
        #pragma unroll
        for (int i = 0; i < 8; i++) {
            int j = tid + i * 128;
            int r = j >> 4, c4 = (j & 15) << 2;
            float4 kv = *(const float4*)&Kg[(size_t)(kt * 64 + r) * HD + c4];
            float4 vv = *(const float4*)&Vg[(size_t)(kt * 64 + r) * HD + c4];
            float4 h4, l4;
            split_tf32(kv.x, h4.x, l4.x); split_tf32(kv.y, h4.y, l4.y);
            split_tf32(kv.z, h4.z, l4.z); split_tf32(kv.w, h4.w, l4.w);
            *(float4*)&sKh[r * KSTR + c4] = h4;
            *(float4*)&sKl[r * KSTR + c4] = l4;
            split_tf32(vv.x, h4.x, l4.x); split_tf32(vv.y, h4.y, l4.y);
            split_tf32(vv.z, h4.z, l4.z); split_tf32(vv.w, h4.w, l4.w);
            *(float4*)&sVh[r * VSTR + c4] = h4;
            *(float4*)&sVl[r * VSTR + c4] = l4;
        }
        __syncthreads();

        // S = Qs @ K^T (3xTF32)
        float sacc[8][4];
        #pragma unroll
        for (int j = 0; j < 8; j++)
            #pragma unroll
            for (int c = 0; c < 4; c++) sacc[j][c] = 0.f;

        #pragma unroll
        for (int kk = 0; kk < 8; kk++) {
            const int k0 = kk * 8;
            #pragma unroll
            for (int j = 0; j < 8; j++) {
                const int brow = j * 8 + g4;
                uint32_t bh[2], bl[2];
                bh[0] = __float_as_uint(sKh[brow * KSTR + k0 + t4]);
                bh[1] = __float_as_uint(sKh[brow * KSTR + k0 + t4 + 4]);
                bl[0] = __float_as_uint(sKl[brow * KSTR + k0 + t4]);
                bl[1] = __float_as_uint(sKl[brow * KSTR + k0 + t4 + 4]);
                mma3(sacc[j], qah[kk], qal[kk], bh, bl);
            }
        }

        // mask + exp (no max shift) -> split P into smem; accumulate denom
        #pragma unroll
        for (int j = 0; j < 8; j++) {
            const int col = j * 8 + 2 * t4;
            float p0 = (sacc[j][0] > mean0) ? __expf(sacc[j][0]) : 0.f;
            float p1 = (sacc[j][1] > mean0) ? __expf(sacc[j][1]) : 0.f;
            float p2 = (sacc[j][2] > mean1) ? __expf(sacc[j][2]) : 0.f;
            float p3 = (sacc[j][3] > mean1) ? __expf(sacc[j][3]) : 0.f;
            den0 += p0 + p1;
            den1 += p2 + p3;
            float h0, l0, h1, l1;
            split_tf32(p0, h0, l0); split_tf32(p1, h1, l1);
            *(float2*)&sPh[g4 * KSTR + col] = make_float2(h0, h1);
            *(float2*)&sPl[g4 * KSTR + col] = make_float2(l0, l1);
            split_tf32(p2, h0, l0); split_tf32(p3, h1, l1);
            *(float2*)&sPh[(g4 + 8) * KSTR + col] = make_float2(h0, h1);
            *(float2*)&sPl[(g4 + 8) * KSTR + col] = make_float2(l0, l1);
        }
        __syncwarp();

        // O += P @ V (3xTF32)
        #pragma unroll
        for (int kk = 0; kk < 8; kk++) {
            const int k0 = kk * 8;
            uint32_t ah[4], al[4];
            ah[0] = __float_as_uint(sPh[g4       * KSTR + k0 + t4]);
            ah[1] = __float_as_uint(sPh[(g4 + 8) * KSTR + k0 + t4]);
            ah[2] = __float_as_uint(sPh[g4       * KSTR + k0 + t4 + 4]);
            ah[3] = __float_as_uint(sPh[(g4 + 8) * KSTR + k0 + t4 + 4]);
            al[0] = __float_as_uint(sPl[g4       * KSTR + k0 + t4]);
            al[1] = __float_as_uint(sPl[(g4 + 8) * KSTR + k0 + t4]);
            al[2] = __float_as_uint(sPl[g4       * KSTR + k0 + t4 + 4]);
            al[3] = __float_as_uint(sPl[(g4 + 8) * KSTR + k0 + t4 + 4]);
            #pragma unroll
            for (int j = 0; j < 8; j++) {
                const int bcol = j * 8 + g4;
                uint32_t bh[2], bl[2];
                bh[0] = __float_as_uint(sVh[(k0 + t4)     * VSTR + bcol]);
                bh[1] = __float_as_uint(sVh[(k0 + t4 + 4) * VSTR + bcol]);
                bl[0] = __float_as_uint(sVl[(k0 + t4)     * VSTR + bcol]);
                bl[1] = __float_as_uint(sVl[(k0 + t4 + 4) * VSTR + bcol]);
                mma3(oacc[j], ah, al, bh, bl);
            }
        }
    }

    // reduce denominators across quad, normalize, write out
    #pragma unroll
    for (int o = 1; o <= 2; o <<= 1) {
        den0 += __shfl_xor_sync(0xffffffffu, den0, o);
        den1 += __shfl_xor_sync(0xffffffffu, den1, o);
    }
    const float inv0 = 1.f / den0;
    const float inv1 = 1.f / den1;

    #pragma unroll
    for (int j = 0; j < 8; j++) {
        const int col = j * 8 + 2 * t4;
        *(float2*)&Og[(size_t)row0 * HD + col] =
            make_float2(oacc[j][0] * inv0, oacc[j][1] * inv0);
        *(float2*)&Og[(size_t)row1 * HD + col] =
            make_float2(oacc[j][2] * inv1, oacc[j][3] * inv1);
    }
}

// ---------------------------------------------------------------------------
// Launch
// ---------------------------------------------------------------------------
extern "C" void kernel_launch(void* const* d_in, const int* in_sizes, int n_in,
                              void* d_out, int out_size)
{
    const float* x   = (const float*)d_in[0];
    const float* y   = (const float*)d_in[1];
    const float* q_w = (const float*)d_in[2];
    const float* q_b = (const float*)d_in[3];
    const float* k_w = (const float*)d_in[4];
    const float* k_b = (const float*)d_in[5];
    const float* v_w = (const float*)d_in[6];
    const float* v_b = (const float*)d_in[7];
    const float* o_w = (const float*)d_in[8];
    const float* o_b = (const float*)d_in[9];
    float* out = (float*)d_out;

    float *Qp, *Kp, *Vp, *AO, *KsP;
    cudaGetSymbolAddress((void**)&Qp, g_Qp);
    cudaGetSymbolAddress((void**)&Kp, g_Kp);
    cudaGetSymbolAddress((void**)&Vp, g_Vp);
    cudaGetSymbolAddress((void**)&AO, g_AO);
    cudaGetSymbolAddress((void**)&KsP, g_KsumP);

    static int smem_set = 0;
    if (!smem_set) {
        cudaFuncSetAttribute(attn_fused,
                             cudaFuncAttributeMaxDynamicSharedMemorySize, SM_BYTES);
        smem_set = 1;
    }

    dim3 blk(256);

    // QKV projections
    gemm_nt<<<dim3(4, 32), blk>>>(x, q_w, q_b, Qp, DM, DM, DM);
    gemm_nt<<<dim3(4, 32), blk>>>(y, k_w, k_b, Kp, DM, DM, DM);
    gemm_nt<<<dim3(4, 32), blk>>>(y, v_w, v_b, Vp, DM, DM, DM);

    // K column-sum partials (for mean thresholds)
    ksum_kernel<<<dim3(NG, 8), 256>>>(Kp, KsP);

    // Fused single-pass attention
    attn_fused<<<dim3(SEQ / 64, NG), 128, SM_BYTES>>>(Qp, Kp, Vp, KsP, AO);

    // Output projection
    gemm_nt<<<dim3(4, 32), blk>>>(AO, o_w, o_b, out, DM, DM, DM);
}

// round 7
// speedup vs baseline: 1.4306x; 1.0232x over previous
#include <cuda_runtime.h>
#include <math.h>
#include <stdint.h>

// Problem constants
#define DM   512
#define SEQ  2048
#define BB   2
#define NH   8
#define HD   64
#define MTOK (BB*SEQ)     // 4096 tokens
#define NG   (NH*BB)      // 16 attention groups

#define NORMF 0.04419417382415922f  // 1/sqrt(512)

// Scratch (static device globals; allocation is forbidden)
__device__ float g_Qp[MTOK * DM];
__device__ float g_Kp[MTOK * DM];
__device__ float g_Vp[MTOK * DM];
__device__ float g_AO[MTOK * DM];
__device__ float g_KsumP[NG * 8 * HD];

// ---------------------------------------------------------------------------
// tf32 mma.sync.m16n8k8 + split helpers
// ---------------------------------------------------------------------------
__device__ __forceinline__ void mma_tf32(float* c, const uint32_t* a, const uint32_t* b)
{
    asm volatile(
        "mma.sync.aligned.m16n8k8.row.col.f32.tf32.tf32.f32 "
        "{%0,%1,%2,%3}, {%4,%5,%6,%7}, {%8,%9}, {%0,%1,%2,%3};\n"
        : "+f"(c[0]), "+f"(c[1]), "+f"(c[2]), "+f"(c[3])
        : "r"(a[0]), "r"(a[1]), "r"(a[2]), "r"(a[3]), "r"(b[0]), "r"(b[1]));
}

__device__ __forceinline__ uint32_t to_tf32(float x)
{
    uint32_t r;
    asm("cvt.rna.tf32.f32 %0, %1;\n" : "=r"(r) : "f"(x));
    return r;
}

__device__ __forceinline__ void split_tf32(float x, float& hi, float& lo)
{
    hi = __uint_as_float(to_tf32(x));
    lo = x - hi;
}

__device__ __forceinline__ void mma3(float* c,
                                     const uint32_t* ah, const uint32_t* al,
                                     const uint32_t* bh, const uint32_t* bl)
{
    mma_tf32(c, ah, bl);
    mma_tf32(c, al, bh);
    mma_tf32(c, ah, bh);
}

// ---------------------------------------------------------------------------
// Tensor-core NT projection GEMM (3xTF32):
// C[4096,512] = A[4096,512] @ W[512,512]^T + bias
// 128x128 CTA tile, BK=32, 8 warps (2m x 4n), warp tile 64x32.
// SMEM (dynamic): (hi,lo)-interleaved float2, row stride 36 float2.
// ---------------------------------------------------------------------------
#define PJ_S 36
#define PJ_SMEM_BYTES (2 * 128 * PJ_S * (int)sizeof(float2))   // 73728

__global__ __launch_bounds__(256) void gemm_nt_tc(
    const float* __restrict__ A, const float* __restrict__ W,
    const float* __restrict__ bias, float* __restrict__ C)
{
    extern __shared__ float2 pj_sm[];
    float2* sA = pj_sm;                 // [128][PJ_S]
    float2* sW = pj_sm + 128 * PJ_S;    // [128][PJ_S]

    const int tid  = threadIdx.x;
    const int warp = tid >> 5;
    const int lane = tid & 31;
    const int g4   = lane >> 2;
    const int t4   = lane & 3;
    const int wm   = warp >> 2;   // 0..1
    const int wn   = warp & 3;    // 0..3
    const int m0   = blockIdx.y * 128;
    const int n0   = blockIdx.x * 128;

    float acc[4][4][4];
    #pragma unroll
    for (int mf = 0; mf < 4; mf++)
        #pragma unroll
        for (int nf = 0; nf < 4; nf++)
            #pragma unroll
            for (int c = 0; c < 4; c++) acc[mf][nf][c] = 0.f;

    for (int kt = 0; kt < DM / 32; kt++) {
        const int k0 = kt * 32;
        __syncthreads();
        #pragma unroll
        for (int i = 0; i < 4; i++) {
            int pos = tid + i * 256;          // 0..1023
            int r = pos >> 3, kq = (pos & 7) << 2;
            float4 a = *(const float4*)&A[(size_t)(m0 + r) * DM + k0 + kq];
            float4 w = *(const float4*)&W[(size_t)(n0 + r) * DM + k0 + kq];
            float4 s0, s1;
            split_tf32(a.x, s0.x, s0.y); split_tf32(a.y, s0.z, s0.w);
            split_tf32(a.z, s1.x, s1.y); split_tf32(a.w, s1.z, s1.w);
            *(float4*)&sA[r * PJ_S + kq]     = s0;
            *(float4*)&sA[r * PJ_S + kq + 2] = s1;
            split_tf32(w.x, s0.x, s0.y); split_tf32(w.y, s0.z, s0.w);
            split_tf32(w.z, s1.x, s1.y); split_tf32(w.w, s1.z, s1.w);
            *(float4*)&sW[r * PJ_S + kq]     = s0;
            *(float4*)&sW[r * PJ_S + kq + 2] = s1;
        }
        __syncthreads();

        #pragma unroll
        for (int kk = 0; kk < 4; kk++) {
            const int kc = kk * 8 + t4;
            uint32_t ah[4][4], al[4][4];
            #pragma unroll
            for (int mf = 0; mf < 4; mf++) {
                const int rb = wm * 64 + mf * 16;
                float2 e0 = sA[(rb + g4)     * PJ_S + kc];
                float2 e1 = sA[(rb + g4 + 8) * PJ_S + kc];
                float2 e2 = sA[(rb + g4)     * PJ_S + kc + 4];
                float2 e3 = sA[(rb + g4 + 8) * PJ_S + kc + 4];
                ah[mf][0] = __float_as_uint(e0.x); al[mf][0] = __float_as_uint(e0.y);
                ah[mf][1] = __float_as_uint(e1.x); al[mf][1] = __float_as_uint(e1.y);
                ah[mf][2] = __float_as_uint(e2.x); al[mf][2] = __float_as_uint(e2.y);
                ah[mf][3] = __float_as_uint(e3.x); al[mf][3] = __float_as_uint(e3.y);
            }
            #pragma unroll
            for (int nf = 0; nf < 4; nf++) {
                const int nr = wn * 32 + nf * 8 + g4;
                float2 b0 = sW[nr * PJ_S + kc];
                float2 b1 = sW[nr * PJ_S + kc + 4];
                uint32_t bh[2] = {__float_as_uint(b0.x), __float_as_uint(b1.x)};
                uint32_t bl[2] = {__float_as_uint(b0.y), __float_as_uint(b1.y)};
                #pragma unroll
                for (int mf = 0; mf < 4; mf++)
                    mma3(acc[mf][nf], ah[mf], al[mf], bh, bl);
            }
        }
    }

    #pragma unroll
    for (int nf = 0; nf < 4; nf++) {
        const int col = n0 + wn * 32 + nf * 8 + 2 * t4;
        const float b0 = bias[col], b1 = bias[col + 1];
        #pragma unroll
        for (int mf = 0; mf < 4; mf++) {
            const int r0 = m0 + wm * 64 + mf * 16 + g4;
            *(float2*)&C[(size_t)r0 * DM + col] =
                make_float2(acc[mf][nf][0] + b0, acc[mf][nf][1] + b1);
            *(float2*)&C[(size_t)(r0 + 8) * DM + col] =
                make_float2(acc[mf][nf][2] + b0, acc[mf][nf][3] + b1);
        }
    }
}

// ---------------------------------------------------------------------------
// K column-sum partials
// ---------------------------------------------------------------------------
__global__ __launch_bounds__(256) void ksum_kernel(const float* __restrict__ Kp,
                                                   float* __restrict__ out)
{
    const int g  = blockIdx.x;
    const int ch = blockIdx.y;
    const int d  = threadIdx.x & 63;
    const int rc = threadIdx.x >> 6;
    const float* Kg = Kp + ((size_t)g * SEQ + ch * 256) * HD;
    float s = 0.f;
    #pragma unroll 8
    for (int r = rc; r < 256; r += 4) s += Kg[r * HD + d];
    __shared__ float red[256];
    red[threadIdx.x] = s;
    __syncthreads();
    if (rc == 0)
        out[(g * 8 + ch) * HD + d] = red[d] + red[64 + d] + red[128 + d] + red[192 + d];
}

// ---------------------------------------------------------------------------
// Single-pass fused attention, 3xTF32, (hi,lo)-interleaved SMEM.
// Row stride 68 float2 (s%16==4): conflict-free LDS.64 for both frag patterns.
// ---------------------------------------------------------------------------
#define AT_S 68
#define SM_F2  (64*AT_S + 64*AT_S + 4*16*AT_S)
#define SM_BYTES (SM_F2 * 8)                    // 104448 B

__global__ __launch_bounds__(128, 2) void attn_fused(
    const float* __restrict__ Qp, const float* __restrict__ Kp,
    const float* __restrict__ Vp, const float* __restrict__ KsP,
    float* __restrict__ AO)
{
    extern __shared__ float2 sm2[];
    float2* sK2 = sm2;                    // [64][AT_S]
    float2* sV2 = sK2 + 64 * AT_S;        // [64][AT_S]
    float2* sP_all = sV2 + 64 * AT_S;     // 4 x [16][AT_S]

    const int tid  = threadIdx.x;
    const int warp = tid >> 5;
    const int lane = tid & 31;
    const int g4   = lane >> 2;
    const int t4   = lane & 3;

    const int mt  = blockIdx.x;
    const int grp = blockIdx.y;
    const float* Qg = Qp + (size_t)grp * SEQ * HD;
    const float* Kg = Kp + (size_t)grp * SEQ * HD;
    const float* Vg = Vp + (size_t)grp * SEQ * HD;
    float*       Og = AO + (size_t)grp * SEQ * HD;

    const int m0 = mt * 64;
    const int wrow = warp * 16;
    float2* sP2 = sP_all + warp * 16 * AT_S;

    // --- Q fragments (registers) + row means via K column-sums ---
    const int row0 = m0 + wrow + g4;
    const int row1 = row0 + 8;
    uint32_t qah[8][4], qal[8][4];
    float mdot0 = 0.f, mdot1 = 0.f;

    #pragma unroll
    for (int kk = 0; kk < 8; kk++) {
        #pragma unroll
        for (int e = 0; e < 2; e++) {
            const int col = kk * 8 + t4 + e * 4;
            float ks = 0.f;
            #pragma unroll
            for (int c = 0; c < 8; c++)
                ks += KsP[(grp * 8 + c) * HD + col];
            float q0 = Qg[(size_t)row0 * HD + col];
            float q1 = Qg[(size_t)row1 * HD + col];
            mdot0 += q0 * ks;
            mdot1 += q1 * ks;
            float h, l;
            split_tf32(q0 * NORMF, h, l);
            qah[kk][e * 2] = __float_as_uint(h);
            qal[kk][e * 2] = __float_as_uint(l);
            split_tf32(q1 * NORMF, h, l);
            qah[kk][e * 2 + 1] = __float_as_uint(h);
            qal[kk][e * 2 + 1] = __float_as_uint(l);
        }
    }
    #pragma unroll
    for (int o = 1; o <= 2; o <<= 1) {
        mdot0 += __shfl_xor_sync(0xffffffffu, mdot0, o);
        mdot1 += __shfl_xor_sync(0xffffffffu, mdot1, o);
    }
    const float mean0 = mdot0 * (NORMF / (float)SEQ);
    const float mean1 = mdot1 * (NORMF / (float)SEQ);

    // --- streaming loop ---
    float oacc[8][4];
    #pragma unroll
    for (int j = 0; j < 8; j++)
        #pragma unroll
        for (int c = 0; c < 4; c++) oacc[j][c] = 0.f;
    float den0 = 0.f, den1 = 0.f;

    for (int kt = 0; kt < SEQ / 64; kt++) {
        __syncthreads();
        #pragma unroll
        for (int i = 0; i < 8; i++) {
            int j = tid + i * 128;
            int r = j >> 4, c4 = (j & 15) << 2;
            float4 kv = *(const float4*)&Kg[(size_t)(kt * 64 + r) * HD + c4];
            float4 vv = *(const float4*)&Vg[(size_t)(kt * 64 + r) * HD + c4];
            float4 s0, s1;
            split_tf32(kv.x, s0.x, s0.y); split_tf32(kv.y, s0.z, s0.w);
            split_tf32(kv.z, s1.x, s1.y); split_tf32(kv.w, s1.z, s1.w);
            *(float4*)&sK2[r * AT_S + c4]     = s0;
            *(float4*)&sK2[r * AT_S + c4 + 2] = s1;
            split_tf32(vv.x, s0.x, s0.y); split_tf32(vv.y, s0.z, s0.w);
            split_tf32(vv.z, s1.x, s1.y); split_tf32(vv.w, s1.z, s1.w);
            *(float4*)&sV2[r * AT_S + c4]     = s0;
            *(float4*)&sV2[r * AT_S + c4 + 2] = s1;
        }
        __syncthreads();

        // S = Qs @ K^T (3xTF32)
        float sacc[8][4];
        #pragma unroll
        for (int j = 0; j < 8; j++)
            #pragma unroll
            for (int c = 0; c < 4; c++) sacc[j][c] = 0.f;

        #pragma unroll
        for (int kk = 0; kk < 8; kk++) {
            const int k0 = kk * 8;
            #pragma unroll
            for (int j = 0; j < 8; j++) {
                const int brow = j * 8 + g4;
                float2 b0 = sK2[brow * AT_S + k0 + t4];
                float2 b1 = sK2[brow * AT_S + k0 + t4 + 4];
                uint32_t bh[2] = {__float_as_uint(b0.x), __float_as_uint(b1.x)};
                uint32_t bl[2] = {__float_as_uint(b0.y), __float_as_uint(b1.y)};
                mma3(sacc[j], qah[kk], qal[kk], bh, bl);
            }
        }

        // mask + exp -> split P into smem; accumulate denom
        #pragma unroll
        for (int j = 0; j < 8; j++) {
            float p0 = (sacc[j][0] > mean0) ? __expf(sacc[j][0]) : 0.f;
            float p1 = (sacc[j][1] > mean0) ? __expf(sacc[j][1]) : 0.f;
            float p2 = (sacc[j][2] > mean1) ? __expf(sacc[j][2]) : 0.f;
            float p3 = (sacc[j][3] > mean1) ? __expf(sacc[j][3]) : 0.f;
            den0 += p0 + p1;
            den1 += p2 + p3;
            float4 s;
            split_tf32(p0, s.x, s.y); split_tf32(p1, s.z, s.w);
            *(float4*)&sP2[g4 * AT_S + j * 8 + 2 * t4] = s;
            split_tf32(p2, s.x, s.y); split_tf32(p3, s.z, s.w);
            *(float4*)&sP2[(g4 + 8) * AT_S + j * 8 + 2 * t4] = s;
        }
        __syncwarp();

        // O += P @ V (3xTF32)
        #pragma unroll
        for (int kk = 0; kk < 8; kk++) {
            const int k0 = kk * 8;
            float2 a0 = sP2[g4       * AT_S + k0 + t4];
            float2 a1 = sP2[(g4 + 8) * AT_S + k0 + t4];
            float2 a2 = sP2[g4       * AT_S + k0 + t4 + 4];
            float2 a3 = sP2[(g4 + 8) * AT_S + k0 + t4 + 4];
            uint32_t ah[4] = {__float_as_uint(a0.x), __float_as_uint(a1.x),
                              __float_as_uint(a2.x), __float_as_uint(a3.x)};
            uint32_t al[4] = {__float_as_uint(a0.y), __float_as_uint(a1.y),
                              __float_as_uint(a2.y), __float_as_uint(a3.y)};
            #pragma unroll
            for (int j = 0; j < 8; j++) {
                const int bcol = j * 8 + g4;
                float2 b0 = sV2[(k0 + t4)     * AT_S + bcol];
                float2 b1 = sV2[(k0 + t4 + 4) * AT_S + bcol];
                uint32_t bh[2] = {__float_as_uint(b0.x), __float_as_uint(b1.x)};
                uint32_t bl[2] = {__float_as_uint(b0.y), __float_as_uint(b1.y)};
                mma3(oacc[j], ah, al, bh, bl);
            }
        }
    }

    // reduce denominators, normalize, write out
    #pragma unroll
    for (int o = 1; o <= 2; o <<= 1) {
        den0 += __shfl_xor_sync(0xffffffffu, den0, o);
        den1 += __shfl_xor_sync(0xffffffffu, den1, o);
    }
    const float inv0 = 1.f / den0;
    const float inv1 = 1.f / den1;

    #pragma unroll
    for (int j = 0; j < 8; j++) {
        const int col = j * 8 + 2 * t4;
        *(float2*)&Og[(size_t)row0 * HD + col] =
            make_float2(oacc[j][0] * inv0, oacc[j][1] * inv0);
        *(float2*)&Og[(size_t)row1 * HD + col] =
            make_float2(oacc[j][2] * inv1, oacc[j][3] * inv1);
    }
}

// ---------------------------------------------------------------------------
// Launch
// ---------------------------------------------------------------------------
extern "C" void kernel_launch(void* const* d_in, const int* in_sizes, int n_in,
                              void* d_out, int out_size)
{
    const float* x   = (const float*)d_in[0];
    const float* y   = (const float*)d_in[1];
    const float* q_w = (const float*)d_in[2];
    const float* q_b = (const float*)d_in[3];
    const float* k_w = (const float*)d_in[4];
    const float* k_b = (const float*)d_in[5];
    const float* v_w = (const float*)d_in[6];
    const float* v_b = (const float*)d_in[7];
    const float* o_w = (const float*)d_in[8];
    const float* o_b = (const float*)d_in[9];
    float* out = (float*)d_out;

    float *Qp, *Kp, *Vp, *AO, *KsP;
    cudaGetSymbolAddress((void**)&Qp, g_Qp);
    cudaGetSymbolAddress((void**)&Kp, g_Kp);
    cudaGetSymbolAddress((void**)&Vp, g_Vp);
    cudaGetSymbolAddress((void**)&AO, g_AO);
    cudaGetSymbolAddress((void**)&KsP, g_KsumP);

    static int smem_set = 0;
    if (!smem_set) {
        cudaFuncSetAttribute(attn_fused,
                             cudaFuncAttributeMaxDynamicSharedMemorySize, SM_BYTES);
        cudaFuncSetAttribute(gemm_nt_tc,
                             cudaFuncAttributeMaxDynamicSharedMemorySize, PJ_SMEM_BYTES);
        smem_set = 1;
    }

    // QKV projections (tensor core, 3xTF32)
    gemm_nt_tc<<<dim3(4, 32), 256, PJ_SMEM_BYTES>>>(x, q_w, q_b, Qp);
    gemm_nt_tc<<<dim3(4, 32), 256, PJ_SMEM_BYTES>>>(y, k_w, k_b, Kp);
    gemm_nt_tc<<<dim3(4, 32), 256, PJ_SMEM_BYTES>>>(y, v_w, v_b, Vp);

    // K column-sum partials (for mean thresholds)
    ksum_kernel<<<dim3(NG, 8), 256>>>(Kp, KsP);

    // Fused single-pass attention
    attn_fused<<<dim3(SEQ / 64, NG), 128, SM_BYTES>>>(Qp, Kp, Vp, KsP, AO);

    // Output projection (tensor core, 3xTF32)
    gemm_nt_tc<<<dim3(4, 32), 256, PJ_SMEM_BYTES>>>(AO, o_w, o_b, out);
}